// round 9
// baseline (speedup 1.0000x reference)
#include <cuda_runtime.h>
#include <math.h>

#define NPATHS 8192
#define SEQ    512
#define NSTEP  511
#define HID    128
#define PB     64          // paths per block (2 groups x 32)
#define GP     32          // paths per group
#define NTHR   512
#define NBLK   (NPATHS / PB)

#define MIN_VOL 1e-4f
#define MAX_VOL 5.0f

#define GWS 132   // padded row stride for gw2

// ---- shared memory layout (floats) ----
#define S_FW1 0
#define S_FB1 384
#define S_FW2 512
#define S_FB2 16896
#define S_FW3 17024
#define S_FB3 17280
#define S_GW1 17284
#define S_GB1 17540
#define S_GW2 17668          // 132*128 = 16896
#define S_GB2 34564
#define S_GW3 34692
#define S_GB3 34948
#define S_TS  34952
#define S_A   35464          // 2 x 4096 (H1 per group)
#define S_B   43656          // 2 x 4096 (G1 / delta_z2 per group)
#define S_PF  51848          // 2 x 512 f partials (8 warps x 64)
#define S_PR  52872          // 2 x 512 raw partials
#define S_PC  53896          // 2 x 512 corr partials
#define S_YSH 54920          // 2 x 64
#define S_GV  55048
#define S_DWV 55176
#define S_DRW 55304
#define S_TOT 55432
#define SMEM_BYTES (S_TOT * 4)

// ---- packed f32x2 helpers ----
__device__ __forceinline__ void ffma2(unsigned long long& d, unsigned long long a, unsigned long long b) {
    asm("fma.rn.f32x2 %0, %1, %2, %0;" : "+l"(d) : "l"(a), "l"(b));
}
__device__ __forceinline__ unsigned long long dup2(float w) {
    unsigned long long r;
    asm("mov.b64 %0, {%1, %1};" : "=l"(r) : "f"(w));
    return r;
}
__device__ __forceinline__ float2 upk(unsigned long long u) {
    float2 v;
    asm("mov.b64 {%0, %1}, %2;" : "=f"(v.x), "=f"(v.y) : "l"(u));
    return v;
}

// exp-based sigmoid (accurate; forward path)
__device__ __forceinline__ float sigm(float z) {
    return __fdividef(1.0f, 1.0f + __expf(-z));
}
__device__ __forceinline__ float silu_(float z) { return z * sigm(z); }

// tanh-based sigmoid (Milstein-correction dsilu factors only)
__device__ __forceinline__ float sigm_t(float z) {
    float th;
    asm("tanh.approx.f32 %0, %1;" : "=f"(th) : "f"(0.5f * z));
    return 0.5f * th + 0.5f;
}
__device__ __forceinline__ float dsilu_t(float z) {
    float s = sigm_t(z);
    return s * (1.0f + z * (1.0f - s));
}

// forward GEMM (per group, A stride GP): acc[p][j] += sum_k A[k][p] * W[k][j]
__device__ __forceinline__ void gemm_fwd(const float* __restrict__ sA,
                                         const float* __restrict__ sW, int ws,
                                         int pg, int cg, unsigned long long acc[8]) {
#pragma unroll 2
    for (int k4 = 0; k4 < HID; k4 += 4) {
        ulonglong2 h[4];
#pragma unroll
        for (int u = 0; u < 4; ++u)
            h[u] = *(const ulonglong2*)(sA + (k4 + u) * GP + pg * 4);
#pragma unroll
        for (int u = 0; u < 4; ++u) {
            float4 w = *(const float4*)(sW + (k4 + u) * ws + cg * 4);
            unsigned long long w0 = dup2(w.x), w1 = dup2(w.y), w2 = dup2(w.z), w3 = dup2(w.w);
            ffma2(acc[0], h[u].x, w0); ffma2(acc[1], h[u].y, w0);
            ffma2(acc[2], h[u].x, w1); ffma2(acc[3], h[u].y, w1);
            ffma2(acc[4], h[u].x, w2); ffma2(acc[5], h[u].y, w2);
            ffma2(acc[6], h[u].x, w3); ffma2(acc[7], h[u].y, w3);
        }
    }
}

// backward GEMM (per group): acc[p][i] += sum_k B[k][p] * W[i][k]
__device__ __forceinline__ void gemm_bwd(const float* __restrict__ sB,
                                         const float* __restrict__ sW,
                                         int pg, int cg, unsigned long long acc[8]) {
#pragma unroll 2
    for (int k4 = 0; k4 < HID; k4 += 4) {
        ulonglong2 h[4];
#pragma unroll
        for (int u = 0; u < 4; ++u)
            h[u] = *(const ulonglong2*)(sB + (k4 + u) * GP + pg * 4);
#pragma unroll
        for (int c = 0; c < 4; ++c) {
            float4 w = *(const float4*)(sW + (cg * 4 + c) * GWS + k4);
            unsigned long long wd;
            wd = dup2(w.x); ffma2(acc[2 * c], h[0].x, wd); ffma2(acc[2 * c + 1], h[0].y, wd);
            wd = dup2(w.y); ffma2(acc[2 * c], h[1].x, wd); ffma2(acc[2 * c + 1], h[1].y, wd);
            wd = dup2(w.z); ffma2(acc[2 * c], h[2].x, wd); ffma2(acc[2 * c + 1], h[2].y, wd);
            wd = dup2(w.w); ffma2(acc[2 * c], h[3].x, wd); ffma2(acc[2 * c + 1], h[3].y, wd);
        }
    }
}

// reduce 8 partials over the 4 cg-subgroups of a warp, 8 lanes store to P[gw*64 + pg*8..+7]
__device__ __forceinline__ void part_reduce_store(float part[8], float* __restrict__ dst,
                                                  int lane, int gw, int pg) {
#pragma unroll
    for (int v = 0; v < 8; ++v) {
        part[v] += __shfl_xor_sync(0xffffffffu, part[v], 8);
        part[v] += __shfl_xor_sync(0xffffffffu, part[v], 16);
    }
    if ((lane >> 3) == 0) {
        float4 o0 = {part[0], part[1], part[2], part[3]};
        float4 o1 = {part[4], part[5], part[6], part[7]};
        *(float4*)(dst + gw * 64 + pg * 8) = o0;
        *(float4*)(dst + gw * 64 + pg * 8 + 4) = o1;
    }
}

__global__ void __launch_bounds__(NTHR, 1) sde_kernel(
    const float* __restrict__ y0, const float* __restrict__ ts, const float* __restrict__ dW,
    const float* __restrict__ fw1, const float* __restrict__ fb1,
    const float* __restrict__ fw2, const float* __restrict__ fb2,
    const float* __restrict__ fw3, const float* __restrict__ fb3,
    const float* __restrict__ gw1, const float* __restrict__ gb1,
    const float* __restrict__ gw2, const float* __restrict__ gb2,
    const float* __restrict__ gw3, const float* __restrict__ gb3,
    float* __restrict__ out) {
    extern __shared__ float sm[];
    const int tid = threadIdx.x;
    const int p0 = blockIdx.x * PB;

    {
        auto cp = [&](int dst, const float* src, int n) {
            for (int i = tid; i < n; i += NTHR) sm[dst + i] = src[i];
        };
        cp(S_FW1, fw1, 384);   cp(S_FB1, fb1, 128);
        cp(S_FW2, fw2, 16384); cp(S_FB2, fb2, 128);
        cp(S_FW3, fw3, 256);   cp(S_FB3, fb3, 2);
        cp(S_GW1, gw1, 256);   cp(S_GB1, gb1, 128);
        cp(S_GB2, gb2, 128);
        cp(S_GW3, gw3, 256);   cp(S_GB3, gb3, 2);
        cp(S_TS, ts, SEQ);
        for (int i = tid; i < 16384; i += NTHR)
            sm[S_GW2 + (i >> 7) * GWS + (i & 127)] = gw2[i];
    }
    if (tid < PB * 2) {
        float v = y0[p0 * 2 + tid];
        sm[S_YSH + tid] = v;
        out[(size_t)(p0 + (tid >> 1)) * (SEQ * 2) + (tid & 1)] = v;
    }
    __syncthreads();

    // ---- group decomposition: 2 independent pipelines of 8 warps / 32 paths ----
    const int grp = tid >> 8;          // 0 or 1
    const int gt = tid & 255;          // thread in group
    const int lane = tid & 31;
    const int gw = gt >> 5;            // warp in group 0..7
    const int pg = lane & 7;           // 8 path groups x 4 paths = 32
    const int cg = (gw << 2) | (lane >> 3);  // 32 col groups x 4 cols = 128
    const int barid = grp + 1;

    float* const gA = sm + S_A + grp * 4096;
    float* const gB = sm + S_B + grp * 4096;
    float* const gPF = sm + S_PF + grp * 512;
    float* const gPR = sm + S_PR + grp * 512;
    float* const gPC = sm + S_PC + grp * 512;
    float* const gY  = sm + S_YSH + grp * 64;
    float* const gGV = sm + S_GV + grp * 64;
    float* const gDW = sm + S_DWV + grp * 64;
    float* const gDR = sm + S_DRW + grp * 64;
    const int gp0 = p0 + grp * GP;

#define GBAR() asm volatile("bar.sync %0, 256;" :: "r"(barid) : "memory")

    for (int t = 0; t < NSTEP; ++t) {
        const float dt = sm[S_TS + t + 1] - sm[S_TS + t];
        const float sqdt = sqrtf(dt);

        // pass1: H1 -> gA, G1 -> gB, dW prefetch
        if (gt < GP * 2)
            gDW[gt] = dW[(size_t)t * (NPATHS * 2) + gp0 * 2 + gt] * sqdt;
#pragma unroll
        for (int it = 0; it < 4; ++it) {
            int i4 = gt + it * 256;            // 1024 float4 tasks
            int j = i4 >> 3, pb = (i4 & 7) * 4;
            float4 y01 = *(const float4*)(gY + pb * 2);
            float4 y23 = *(const float4*)(gY + pb * 2 + 4);
            float fa = sm[S_FW1 + j], fb = sm[S_FW1 + 128 + j], fs = sm[S_FW1 + 256 + j];
            float fbb = sm[S_FB1 + j];
            float4 oF;
            oF.x = silu_(fbb + y01.x * fa + y01.y * fb + (y01.x - y01.y) * fs);
            oF.y = silu_(fbb + y01.z * fa + y01.w * fb + (y01.z - y01.w) * fs);
            oF.z = silu_(fbb + y23.x * fa + y23.y * fb + (y23.x - y23.y) * fs);
            oF.w = silu_(fbb + y23.z * fa + y23.w * fb + (y23.z - y23.w) * fs);
            *(float4*)(gA + j * GP + pb) = oF;
            float ga = sm[S_GW1 + j], gb = sm[S_GW1 + 128 + j], gbb = sm[S_GB1 + j];
            float4 oG;
            oG.x = silu_(gbb + y01.x * ga + y01.y * gb);
            oG.y = silu_(gbb + y01.z * ga + y01.w * gb);
            oG.z = silu_(gbb + y23.x * ga + y23.y * gb);
            oG.w = silu_(gbb + y23.z * ga + y23.w * gb);
            *(float4*)(gB + j * GP + pb) = oG;
        }
        GBAR();

        // GEMM2: z = H1 @ fw2 + fb2; f-partials = silu(z) @ fw3 -> gPF
        {
            unsigned long long acc[8] = {};
            gemm_fwd(gA, sm + S_FW2, HID, pg, cg, acc);
            float part[8] = {0, 0, 0, 0, 0, 0, 0, 0};
#pragma unroll
            for (int c = 0; c < 4; ++c) {
                int j = cg * 4 + c;
                float bb = sm[S_FB2 + j];
                float w0 = sm[S_FW3 + j * 2], w1 = sm[S_FW3 + j * 2 + 1];
                float2 a = upk(acc[2 * c]), b = upk(acc[2 * c + 1]);
                float h0 = silu_(a.x + bb), h1 = silu_(a.y + bb);
                float h2 = silu_(b.x + bb), h3 = silu_(b.y + bb);
                part[0] += h0 * w0; part[1] += h0 * w1;
                part[2] += h1 * w0; part[3] += h1 * w1;
                part[4] += h2 * w0; part[5] += h2 * w1;
                part[6] += h3 * w0; part[7] += h3 * w1;
            }
            part_reduce_store(part, gPF, lane, gw, pg);
        }

        // GEMM5 (no barrier; reads gB only): z2 in regs; raw-partials -> gPR
        float zr[16];
        {
            unsigned long long acc[8] = {};
            gemm_fwd(gB, sm + S_GW2, GWS, pg, cg, acc);
            float part[8] = {0, 0, 0, 0, 0, 0, 0, 0};
#pragma unroll
            for (int c = 0; c < 4; ++c) {
                int j = cg * 4 + c;
                float bb = sm[S_GB2 + j];
                float w0 = sm[S_GW3 + j * 2], w1 = sm[S_GW3 + j * 2 + 1];
                float2 a = upk(acc[2 * c]), b = upk(acc[2 * c + 1]);
                zr[c * 4 + 0] = a.x + bb; zr[c * 4 + 1] = a.y + bb;
                zr[c * 4 + 2] = b.x + bb; zr[c * 4 + 3] = b.y + bb;
                float g0 = silu_(zr[c * 4 + 0]), g1 = silu_(zr[c * 4 + 1]);
                float g2 = silu_(zr[c * 4 + 2]), g3 = silu_(zr[c * 4 + 3]);
                part[0] += g0 * w0; part[1] += g0 * w1;
                part[2] += g1 * w0; part[3] += g1 * w1;
                part[4] += g2 * w0; part[5] += g2 * w1;
                part[6] += g3 * w0; part[7] += g3 * w1;
            }
            part_reduce_store(part, gPR, lane, gw, pg);
        }
        GBAR();

        // Milstein per-path scalars (gt < 64)
        if (gt < 64) {
            float raw = sm[S_GB3 + (gt & 1)];
#pragma unroll
            for (int g = 0; g < 8; ++g) raw += gPR[g * 64 + gt];
            float dw = gDW[gt];
            float sp = fmaxf(raw, 0.0f) + log1pf(__expf(-fabsf(raw)));
            float g = fminf(fmaxf(sp, MIN_VOL), MAX_VOL);
            float mask = (sp > MIN_VOL && sp < MAX_VOL) ? 1.0f : 0.0f;
            float v = 0.5f * (dw * dw - dt);
            gDR[gt] = v * g * sigm(raw) * mask;
            gGV[gt] = g;
        }
        GBAR();

        // pass8: delta_z2 = dsilu(z2_reg) * (delta_raw @ gw3^T) -> gB
#pragma unroll
        for (int c = 0; c < 4; ++c) {
            int j = cg * 4 + c;
            float g0 = sm[S_GW3 + j * 2], g1 = sm[S_GW3 + j * 2 + 1];
            float4 o;
            float* op = &o.x;
#pragma unroll
            for (int q = 0; q < 4; ++q) {
                int p = pg * 4 + q;
                float u = gDR[p * 2] * g0 + gDR[p * 2 + 1] * g1;
                op[q] = dsilu_t(zr[c * 4 + q]) * u;
            }
            *(float4*)(gB + j * GP + pg * 4) = o;
        }
        GBAR();

        // GEMM9: dz1 = (delta_z2 @ gw2^T) * dsilu(z1); corr-partials -> gPC
        {
            unsigned long long acc[8] = {};
            gemm_bwd(gB, sm + S_GW2, pg, cg, acc);
            float part[8] = {0, 0, 0, 0, 0, 0, 0, 0};
#pragma unroll
            for (int c = 0; c < 4; ++c) {
                int i = cg * 4 + c;
                float w0 = sm[S_GW1 + i], w1 = sm[S_GW1 + 128 + i], bb = sm[S_GB1 + i];
                float2 a = upk(acc[2 * c]), b = upk(acc[2 * c + 1]);
                float vv[4] = {a.x, a.y, b.x, b.y};
#pragma unroll
                for (int q = 0; q < 4; ++q) {
                    int p = pg * 4 + q;
                    float z1 = gY[p * 2] * w0 + gY[p * 2 + 1] * w1 + bb;
                    float dz = vv[q] * dsilu_t(z1);
                    part[q * 2 + 0] += dz * w0;
                    part[q * 2 + 1] += dz * w1;
                }
            }
            part_reduce_store(part, gPC, lane, gw, pg);
        }
        GBAR();

        // final: y update + output (gt < 64)
        if (gt < 64) {
            float fv = sm[S_FB3 + (gt & 1)], corr = 0.0f;
#pragma unroll
            for (int g = 0; g < 8; ++g) {
                fv += gPF[g * 64 + gt];
                corr += gPC[g * 64 + gt];
            }
            float y1 = gY[gt] + fv * dt + gGV[gt] * gDW[gt] + corr;
            gY[gt] = y1;
            out[(size_t)(gp0 + (gt >> 1)) * (SEQ * 2) + (size_t)(t + 1) * 2 + (gt & 1)] = y1;
        }
        GBAR();
    }
#undef GBAR
}

extern "C" void kernel_launch(void* const* d_in, const int* in_sizes, int n_in,
                              void* d_out, int out_size) {
    (void)in_sizes; (void)n_in; (void)out_size;
    cudaFuncSetAttribute(sde_kernel, cudaFuncAttributeMaxDynamicSharedMemorySize, SMEM_BYTES);
    sde_kernel<<<NBLK, NTHR, SMEM_BYTES>>>(
        (const float*)d_in[0], (const float*)d_in[1], (const float*)d_in[2],
        (const float*)d_in[3], (const float*)d_in[4], (const float*)d_in[5],
        (const float*)d_in[6], (const float*)d_in[7], (const float*)d_in[8],
        (const float*)d_in[9], (const float*)d_in[10], (const float*)d_in[11],
        (const float*)d_in[12], (const float*)d_in[13], (const float*)d_in[14],
        (float*)d_out);
}

// round 10
// speedup vs baseline: 1.1474x; 1.1474x over previous
#include <cuda_runtime.h>
#include <math.h>

#define NPATHS 8192
#define SEQ    512
#define NSTEP  511
#define HID    128
#define PB     64
#define NTHR   512
#define NBLK   (NPATHS / PB)

#define MIN_VOL 1e-4f
#define MAX_VOL 5.0f

#define GWS 132   // padded row stride for gw2

// ---- shared memory layout (floats) ----
#define S_FW1 0
#define S_FB1 384
#define S_FW2 512
#define S_FB2 16896
#define S_FW3 17024
#define S_FB3 17280
#define S_GW1 17284
#define S_GB1 17540
#define S_GW2 17668          // 132*128 = 16896
#define S_GB2 34564
#define S_GW3 34692
#define S_GB3 34948
#define S_TS  34952
#define S_A   35464          // 8192: H1, then dsilu(z2)
#define S_B   43656          // 8192: G1, then delta_z2
#define S_PF  51848          // 1024: f partials (8 warps x 128)
#define S_PR  52872          // 1024: raw partials
#define S_PC  53896          // 1024: corr partials
#define S_YSH 54920
#define S_GV  55048
#define S_DWV 55176
#define S_DRW 55304
#define S_TOT 55432
#define SMEM_BYTES (S_TOT * 4)

// ---- packed f32x2 helpers ----
__device__ __forceinline__ void ffma2(unsigned long long& d, unsigned long long a, unsigned long long b) {
    asm("fma.rn.f32x2 %0, %1, %2, %0;" : "+l"(d) : "l"(a), "l"(b));
}
__device__ __forceinline__ unsigned long long dup2(float w) {
    unsigned long long r;
    asm("mov.b64 %0, {%1, %1};" : "=l"(r) : "f"(w));
    return r;
}
__device__ __forceinline__ float2 upk(unsigned long long u) {
    float2 v;
    asm("mov.b64 {%0, %1}, %2;" : "=f"(v.x), "=f"(v.y) : "l"(u));
    return v;
}

// exp-based sigmoid (accurate; forward path)
__device__ __forceinline__ float sigm(float z) {
    return __fdividef(1.0f, 1.0f + __expf(-z));
}
__device__ __forceinline__ float silu_(float z) { return z * sigm(z); }

// tanh-based sigmoid (Milstein-correction dsilu factors only)
__device__ __forceinline__ float sigm_t(float z) {
    float th;
    asm("tanh.approx.f32 %0, %1;" : "=f"(th) : "f"(0.5f * z));
    return 0.5f * th + 0.5f;
}
__device__ __forceinline__ float dsilu_t(float z) {
    float s = sigm_t(z);
    return s * (1.0f + z * (1.0f - s));
}

// forward GEMM, thread tile 4 paths x 8 cols (256 threads cover 64x128)
__device__ __forceinline__ void gemm_fwd8(const float* __restrict__ sA,
                                          const float* __restrict__ sW, int ws,
                                          int pg, int cg, unsigned long long acc[16]) {
#pragma unroll 2
    for (int k4 = 0; k4 < HID; k4 += 4) {
        ulonglong2 h[4];
#pragma unroll
        for (int u = 0; u < 4; ++u)
            h[u] = *(const ulonglong2*)(sA + (k4 + u) * PB + pg * 4);
#pragma unroll
        for (int u = 0; u < 4; ++u) {
            float4 wa = *(const float4*)(sW + (k4 + u) * ws + cg * 8);
            float4 wb = *(const float4*)(sW + (k4 + u) * ws + cg * 8 + 4);
            unsigned long long d0 = dup2(wa.x), d1 = dup2(wa.y), d2 = dup2(wa.z), d3 = dup2(wa.w);
            unsigned long long d4 = dup2(wb.x), d5 = dup2(wb.y), d6 = dup2(wb.z), d7 = dup2(wb.w);
            ffma2(acc[0],  h[u].x, d0); ffma2(acc[1],  h[u].y, d0);
            ffma2(acc[2],  h[u].x, d1); ffma2(acc[3],  h[u].y, d1);
            ffma2(acc[4],  h[u].x, d2); ffma2(acc[5],  h[u].y, d2);
            ffma2(acc[6],  h[u].x, d3); ffma2(acc[7],  h[u].y, d3);
            ffma2(acc[8],  h[u].x, d4); ffma2(acc[9],  h[u].y, d4);
            ffma2(acc[10], h[u].x, d5); ffma2(acc[11], h[u].y, d5);
            ffma2(acc[12], h[u].x, d6); ffma2(acc[13], h[u].y, d6);
            ffma2(acc[14], h[u].x, d7); ffma2(acc[15], h[u].y, d7);
        }
    }
}

// backward GEMM (W transposed, rows contiguous stride GWS), tile 4 x 8
__device__ __forceinline__ void gemm_bwd8(const float* __restrict__ sB,
                                          const float* __restrict__ sW,
                                          int pg, int cg, unsigned long long acc[16]) {
#pragma unroll 2
    for (int k4 = 0; k4 < HID; k4 += 4) {
        ulonglong2 h[4];
#pragma unroll
        for (int u = 0; u < 4; ++u)
            h[u] = *(const ulonglong2*)(sB + (k4 + u) * PB + pg * 4);
#pragma unroll
        for (int c = 0; c < 8; ++c) {
            float4 w = *(const float4*)(sW + (cg * 8 + c) * GWS + k4);
            unsigned long long wd;
            wd = dup2(w.x); ffma2(acc[2 * c], h[0].x, wd); ffma2(acc[2 * c + 1], h[0].y, wd);
            wd = dup2(w.y); ffma2(acc[2 * c], h[1].x, wd); ffma2(acc[2 * c + 1], h[1].y, wd);
            wd = dup2(w.z); ffma2(acc[2 * c], h[2].x, wd); ffma2(acc[2 * c + 1], h[2].y, wd);
            wd = dup2(w.w); ffma2(acc[2 * c], h[3].x, wd); ffma2(acc[2 * c + 1], h[3].y, wd);
        }
    }
}

// reduce partials over the 2 cg-subgroups of a warp (lane bit 4), store 8 floats/lane
__device__ __forceinline__ void reduce16_store(float part[8], float* __restrict__ dst,
                                               int lane, int w) {
#pragma unroll
    for (int v = 0; v < 8; ++v)
        part[v] += __shfl_xor_sync(0xffffffffu, part[v], 16);
    if (lane < 16) {
        float4 o0 = {part[0], part[1], part[2], part[3]};
        float4 o1 = {part[4], part[5], part[6], part[7]};
        *(float4*)(dst + w * 128 + lane * 8) = o0;
        *(float4*)(dst + w * 128 + lane * 8 + 4) = o1;
    }
}

__global__ void __launch_bounds__(NTHR, 1) sde_kernel(
    const float* __restrict__ y0, const float* __restrict__ ts, const float* __restrict__ dW,
    const float* __restrict__ fw1, const float* __restrict__ fb1,
    const float* __restrict__ fw2, const float* __restrict__ fb2,
    const float* __restrict__ fw3, const float* __restrict__ fb3,
    const float* __restrict__ gw1, const float* __restrict__ gb1,
    const float* __restrict__ gw2, const float* __restrict__ gb2,
    const float* __restrict__ gw3, const float* __restrict__ gb3,
    float* __restrict__ out) {
    extern __shared__ float sm[];
    const int tid = threadIdx.x;
    const int p0 = blockIdx.x * PB;

    {
        auto cp = [&](int dst, const float* src, int n) {
            for (int i = tid; i < n; i += NTHR) sm[dst + i] = src[i];
        };
        cp(S_FW1, fw1, 384);   cp(S_FB1, fb1, 128);
        cp(S_FW2, fw2, 16384); cp(S_FB2, fb2, 128);
        cp(S_FW3, fw3, 256);   cp(S_FB3, fb3, 2);
        cp(S_GW1, gw1, 256);   cp(S_GB1, gb1, 128);
        cp(S_GB2, gb2, 128);
        cp(S_GW3, gw3, 256);   cp(S_GB3, gb3, 2);
        cp(S_TS, ts, SEQ);
        for (int i = tid; i < 16384; i += NTHR)
            sm[S_GW2 + (i >> 7) * GWS + (i & 127)] = gw2[i];
    }
    if (tid < PB * 2) {
        float v = y0[p0 * 2 + tid];
        sm[S_YSH + tid] = v;
        out[(size_t)(p0 + (tid >> 1)) * (SEQ * 2) + (tid & 1)] = v;
    }
    __syncthreads();

    const int lane = tid & 31;
    const int w8 = tid >> 5;          // warp id (GEMM warps: 0..7)
    const int pg = tid & 15;          // 16 path groups x 4 paths
    const int cg = tid >> 4;          // col group 0..15 (valid for tid<256), 8 cols each

    for (int t = 0; t < NSTEP; ++t) {
        const float dt = sm[S_TS + t + 1] - sm[S_TS + t];
        const float sqdt = sqrtf(dt);

        // pass1 (all 512): H1 -> A, G1 -> B, dW prefetch
        if (tid < PB * 2)
            sm[S_DWV + tid] = dW[(size_t)t * (NPATHS * 2) + p0 * 2 + tid] * sqdt;
#pragma unroll
        for (int it = 0; it < 4; ++it) {
            int i4 = tid + it * NTHR;          // 2048 float4 tasks
            int j = i4 >> 4, pb = (i4 & 15) * 4;
            float4 y01 = *(const float4*)(sm + S_YSH + pb * 2);
            float4 y23 = *(const float4*)(sm + S_YSH + pb * 2 + 4);
            float fa = sm[S_FW1 + j], fb = sm[S_FW1 + 128 + j], fs = sm[S_FW1 + 256 + j];
            float fbb = sm[S_FB1 + j];
            float4 oF;
            oF.x = silu_(fbb + y01.x * fa + y01.y * fb + (y01.x - y01.y) * fs);
            oF.y = silu_(fbb + y01.z * fa + y01.w * fb + (y01.z - y01.w) * fs);
            oF.z = silu_(fbb + y23.x * fa + y23.y * fb + (y23.x - y23.y) * fs);
            oF.w = silu_(fbb + y23.z * fa + y23.w * fb + (y23.z - y23.w) * fs);
            *(float4*)(sm + S_A + j * PB + pb) = oF;
            float ga = sm[S_GW1 + j], gb = sm[S_GW1 + 128 + j], gbb = sm[S_GB1 + j];
            float4 oG;
            oG.x = silu_(gbb + y01.x * ga + y01.y * gb);
            oG.y = silu_(gbb + y01.z * ga + y01.w * gb);
            oG.z = silu_(gbb + y23.x * ga + y23.y * gb);
            oG.w = silu_(gbb + y23.z * ga + y23.w * gb);
            *(float4*)(sm + S_B + j * PB + pb) = oG;
        }
        __syncthreads();

        // GEMM phase: only warps 0..7 (256 threads), tile 4x8
        if (tid < 256) {
            // GEMM2: z = H1 @ fw2 + fb2; f-partials = silu(z) @ fw3 -> PF
            {
                unsigned long long acc[16] = {};
                gemm_fwd8(sm + S_A, sm + S_FW2, HID, pg, cg, acc);
                float part[8] = {0, 0, 0, 0, 0, 0, 0, 0};
#pragma unroll
                for (int c = 0; c < 8; ++c) {
                    int j = cg * 8 + c;
                    float bb = sm[S_FB2 + j];
                    float w0 = sm[S_FW3 + j * 2], w1 = sm[S_FW3 + j * 2 + 1];
                    float2 a = upk(acc[2 * c]), b = upk(acc[2 * c + 1]);
                    float h0 = silu_(a.x + bb), h1 = silu_(a.y + bb);
                    float h2 = silu_(b.x + bb), h3 = silu_(b.y + bb);
                    part[0] += h0 * w0; part[1] += h0 * w1;
                    part[2] += h1 * w0; part[3] += h1 * w1;
                    part[4] += h2 * w0; part[5] += h2 * w1;
                    part[6] += h3 * w0; part[7] += h3 * w1;
                }
                reduce16_store(part, sm + S_PF, lane, w8);
            }
            // all GEMM warps must finish reading A (GEMM2) before GEMM5 writes s2 into A
            asm volatile("bar.sync 1, 256;" ::: "memory");

            // GEMM5: z2 = G1 @ gw2 + gb2; raw-partials = silu(z2) @ gw3 -> PR;
            // store s2 = dsilu(z2) -> A (consumed by pass8)
            {
                unsigned long long acc[16] = {};
                gemm_fwd8(sm + S_B, sm + S_GW2, GWS, pg, cg, acc);
                float part[8] = {0, 0, 0, 0, 0, 0, 0, 0};
#pragma unroll
                for (int c = 0; c < 8; ++c) {
                    int j = cg * 8 + c;
                    float bb = sm[S_GB2 + j];
                    float w0 = sm[S_GW3 + j * 2], w1 = sm[S_GW3 + j * 2 + 1];
                    float2 a = upk(acc[2 * c]), b = upk(acc[2 * c + 1]);
                    float z0 = a.x + bb, z1 = a.y + bb, z2 = b.x + bb, z3 = b.y + bb;
                    float g0 = silu_(z0), g1 = silu_(z1), g2 = silu_(z2), g3 = silu_(z3);
                    part[0] += g0 * w0; part[1] += g0 * w1;
                    part[2] += g1 * w0; part[3] += g1 * w1;
                    part[4] += g2 * w0; part[5] += g2 * w1;
                    part[6] += g3 * w0; part[7] += g3 * w1;
                    float4 s2 = {dsilu_t(z0), dsilu_t(z1), dsilu_t(z2), dsilu_t(z3)};
                    *(float4*)(sm + S_A + j * PB + pg * 4) = s2;
                }
                reduce16_store(part, sm + S_PR, lane, w8);
            }
        }
        __syncthreads();

        // Milstein per-path scalars (tid<128)
        if (tid < 128) {
            float raw = sm[S_GB3 + (tid & 1)];
#pragma unroll
            for (int g = 0; g < 8; ++g) raw += sm[S_PR + g * 128 + tid];
            float dw = sm[S_DWV + tid];
            float sp = fmaxf(raw, 0.0f) + log1pf(__expf(-fabsf(raw)));
            float g = fminf(fmaxf(sp, MIN_VOL), MAX_VOL);
            float mask = (sp > MIN_VOL && sp < MAX_VOL) ? 1.0f : 0.0f;
            float v = 0.5f * (dw * dw - dt);
            sm[S_DRW + tid] = v * g * sigm(raw) * mask;
            sm[S_GV + tid] = g;
        }
        __syncthreads();

        // pass8 (all 512): delta_z2 = s2(A) * (delta_raw @ gw3^T) -> B
#pragma unroll
        for (int it = 0; it < 4; ++it) {
            int i4 = tid + it * NTHR;
            int j = i4 >> 4, pb = (i4 & 15) * 4;
            float g0 = sm[S_GW3 + j * 2], g1 = sm[S_GW3 + j * 2 + 1];
            float4 s2 = *(const float4*)(sm + S_A + j * PB + pb);
            float4 dr01 = *(const float4*)(sm + S_DRW + pb * 2);
            float4 dr23 = *(const float4*)(sm + S_DRW + pb * 2 + 4);
            float4 o;
            o.x = s2.x * (dr01.x * g0 + dr01.y * g1);
            o.y = s2.y * (dr01.z * g0 + dr01.w * g1);
            o.z = s2.z * (dr23.x * g0 + dr23.y * g1);
            o.w = s2.w * (dr23.z * g0 + dr23.w * g1);
            *(float4*)(sm + S_B + j * PB + pb) = o;
        }
        __syncthreads();

        // GEMM9 (tid<256): dz1 = (delta_z2 @ gw2^T) * dsilu(z1); corr-partials -> PC
        if (tid < 256) {
            unsigned long long acc[16] = {};
            gemm_bwd8(sm + S_B, sm + S_GW2, pg, cg, acc);
            float part[8] = {0, 0, 0, 0, 0, 0, 0, 0};
#pragma unroll
            for (int c = 0; c < 8; ++c) {
                int i = cg * 8 + c;
                float w0 = sm[S_GW1 + i], w1 = sm[S_GW1 + 128 + i], bb = sm[S_GB1 + i];
                float2 a = upk(acc[2 * c]), b = upk(acc[2 * c + 1]);
                float vv[4] = {a.x, a.y, b.x, b.y};
#pragma unroll
                for (int q = 0; q < 4; ++q) {
                    int p = pg * 4 + q;
                    float z1 = sm[S_YSH + p * 2] * w0 + sm[S_YSH + p * 2 + 1] * w1 + bb;
                    float dz = vv[q] * dsilu_t(z1);
                    part[q * 2 + 0] += dz * w0;
                    part[q * 2 + 1] += dz * w1;
                }
            }
            reduce16_store(part, sm + S_PC, lane, w8);
        }
        __syncthreads();

        // final (tid<128): y update + output
        if (tid < 128) {
            float fv = sm[S_FB3 + (tid & 1)], corr = 0.0f;
#pragma unroll
            for (int g = 0; g < 8; ++g) {
                fv += sm[S_PF + g * 128 + tid];
                corr += sm[S_PC + g * 128 + tid];
            }
            float y1 = sm[S_YSH + tid] + fv * dt
                     + sm[S_GV + tid] * sm[S_DWV + tid] + corr;
            sm[S_YSH + tid] = y1;
            out[(size_t)(p0 + (tid >> 1)) * (SEQ * 2) + (size_t)(t + 1) * 2 + (tid & 1)] = y1;
        }
        __syncthreads();
    }
}

extern "C" void kernel_launch(void* const* d_in, const int* in_sizes, int n_in,
                              void* d_out, int out_size) {
    (void)in_sizes; (void)n_in; (void)out_size;
    cudaFuncSetAttribute(sde_kernel, cudaFuncAttributeMaxDynamicSharedMemorySize, SMEM_BYTES);
    sde_kernel<<<NBLK, NTHR, SMEM_BYTES>>>(
        (const float*)d_in[0], (const float*)d_in[1], (const float*)d_in[2],
        (const float*)d_in[3], (const float*)d_in[4], (const float*)d_in[5],
        (const float*)d_in[6], (const float*)d_in[7], (const float*)d_in[8],
        (const float*)d_in[9], (const float*)d_in[10], (const float*)d_in[11],
        (const float*)d_in[12], (const float*)d_in[13], (const float*)d_in[14],
        (float*)d_out);
}

// round 13
// speedup vs baseline: 1.1611x; 1.0119x over previous
#include <cuda_runtime.h>
#include <math.h>

#define NPATHS 8192
#define SEQ    512
#define NSTEP  511
#define HID    128
#define PB     64
#define NTHR   512
#define NBLK   (NPATHS / PB)

#define MIN_VOL 1e-4f
#define MAX_VOL 5.0f

#define GWS 132   // padded row stride for gw2

// ---- shared memory layout (floats) ----
#define S_FW1 0
#define S_FB1 384
#define S_FW2 512
#define S_FB2 16896
#define S_FW3 17024
#define S_FB3 17280
#define S_GW1 17284
#define S_GB1 17540
#define S_GW2 17668          // 132*128 = 16896
#define S_GB2 34564
#define S_GW3 34692
#define S_GB3 34948
#define S_TS  34952
#define S_A   35464          // 8192: H1 (read-only during step by group B)
#define S_B   43656          // 8192: G1 -> delta_z2 (group A)
#define S_PF  51848          // 1024: f partials (8 warps x 128)
#define S_PR  52872          // 1024: raw partials
#define S_PC  53896          // 1024: corr partials
#define S_YSH 54920
#define S_GV  55048
#define S_DWV 55176
#define S_DRW 55304
#define S_TOT 55432
#define SMEM_BYTES (S_TOT * 4)

// ---- packed f32x2 helpers ----
__device__ __forceinline__ void ffma2(unsigned long long& d, unsigned long long a, unsigned long long b) {
    asm("fma.rn.f32x2 %0, %1, %2, %0;" : "+l"(d) : "l"(a), "l"(b));
}
__device__ __forceinline__ unsigned long long dup2(float w) {
    unsigned long long r;
    asm("mov.b64 %0, {%1, %1};" : "=l"(r) : "f"(w));
    return r;
}
__device__ __forceinline__ float2 upk(unsigned long long u) {
    float2 v;
    asm("mov.b64 {%0, %1}, %2;" : "=f"(v.x), "=f"(v.y) : "l"(u));
    return v;
}

// exp-based sigmoid (accurate; forward path)
__device__ __forceinline__ float sigm(float z) {
    return __fdividef(1.0f, 1.0f + __expf(-z));
}
__device__ __forceinline__ float silu_(float z) { return z * sigm(z); }

// tanh-based sigmoid (Milstein-correction dsilu factors only)
__device__ __forceinline__ float sigm_t(float z) {
    float th;
    asm("tanh.approx.f32 %0, %1;" : "=f"(th) : "f"(0.5f * z));
    return 0.5f * th + 0.5f;
}
__device__ __forceinline__ float dsilu_t(float z) {
    float s = sigm_t(z);
    return s * (1.0f + z * (1.0f - s));
}

// forward GEMM, thread tile 4 paths x 8 cols (256 threads cover 64x128)
__device__ __forceinline__ void gemm_fwd8(const float* __restrict__ sA,
                                          const float* __restrict__ sW, int ws,
                                          int pg, int cg, unsigned long long acc[16]) {
#pragma unroll 2
    for (int k4 = 0; k4 < HID; k4 += 4) {
        ulonglong2 h[4];
#pragma unroll
        for (int u = 0; u < 4; ++u)
            h[u] = *(const ulonglong2*)(sA + (k4 + u) * PB + pg * 4);
#pragma unroll
        for (int u = 0; u < 4; ++u) {
            float4 wa = *(const float4*)(sW + (k4 + u) * ws + cg * 8);
            float4 wb = *(const float4*)(sW + (k4 + u) * ws + cg * 8 + 4);
            unsigned long long d0 = dup2(wa.x), d1 = dup2(wa.y), d2 = dup2(wa.z), d3 = dup2(wa.w);
            unsigned long long d4 = dup2(wb.x), d5 = dup2(wb.y), d6 = dup2(wb.z), d7 = dup2(wb.w);
            ffma2(acc[0],  h[u].x, d0); ffma2(acc[1],  h[u].y, d0);
            ffma2(acc[2],  h[u].x, d1); ffma2(acc[3],  h[u].y, d1);
            ffma2(acc[4],  h[u].x, d2); ffma2(acc[5],  h[u].y, d2);
            ffma2(acc[6],  h[u].x, d3); ffma2(acc[7],  h[u].y, d3);
            ffma2(acc[8],  h[u].x, d4); ffma2(acc[9],  h[u].y, d4);
            ffma2(acc[10], h[u].x, d5); ffma2(acc[11], h[u].y, d5);
            ffma2(acc[12], h[u].x, d6); ffma2(acc[13], h[u].y, d6);
            ffma2(acc[14], h[u].x, d7); ffma2(acc[15], h[u].y, d7);
        }
    }
}

// backward GEMM (W transposed, rows contiguous stride GWS), tile 4 x 8
__device__ __forceinline__ void gemm_bwd8(const float* __restrict__ sB,
                                          const float* __restrict__ sW,
                                          int pg, int cg, unsigned long long acc[16]) {
#pragma unroll 2
    for (int k4 = 0; k4 < HID; k4 += 4) {
        ulonglong2 h[4];
#pragma unroll
        for (int u = 0; u < 4; ++u)
            h[u] = *(const ulonglong2*)(sB + (k4 + u) * PB + pg * 4);
#pragma unroll
        for (int c = 0; c < 8; ++c) {
            float4 w = *(const float4*)(sW + (cg * 8 + c) * GWS + k4);
            unsigned long long wd;
            wd = dup2(w.x); ffma2(acc[2 * c], h[0].x, wd); ffma2(acc[2 * c + 1], h[0].y, wd);
            wd = dup2(w.y); ffma2(acc[2 * c], h[1].x, wd); ffma2(acc[2 * c + 1], h[1].y, wd);
            wd = dup2(w.z); ffma2(acc[2 * c], h[2].x, wd); ffma2(acc[2 * c + 1], h[2].y, wd);
            wd = dup2(w.w); ffma2(acc[2 * c], h[3].x, wd); ffma2(acc[2 * c + 1], h[3].y, wd);
        }
    }
}

// reduce partials over the 2 cg-subgroups of a warp (lane bit 4), store 8 floats/lane
__device__ __forceinline__ void reduce16_store(float part[8], float* __restrict__ dst,
                                               int lane, int w) {
#pragma unroll
    for (int v = 0; v < 8; ++v)
        part[v] += __shfl_xor_sync(0xffffffffu, part[v], 16);
    if (lane < 16) {
        float4 o0 = {part[0], part[1], part[2], part[3]};
        float4 o1 = {part[4], part[5], part[6], part[7]};
        *(float4*)(dst + w * 128 + lane * 8) = o0;
        *(float4*)(dst + w * 128 + lane * 8 + 4) = o1;
    }
}

__global__ void __launch_bounds__(NTHR, 1) sde_kernel(
    const float* __restrict__ y0, const float* __restrict__ ts, const float* __restrict__ dW,
    const float* __restrict__ fw1, const float* __restrict__ fb1,
    const float* __restrict__ fw2, const float* __restrict__ fb2,
    const float* __restrict__ fw3, const float* __restrict__ fb3,
    const float* __restrict__ gw1, const float* __restrict__ gb1,
    const float* __restrict__ gw2, const float* __restrict__ gb2,
    const float* __restrict__ gw3, const float* __restrict__ gb3,
    float* __restrict__ out) {
    extern __shared__ float sm[];
    const int tid = threadIdx.x;
    const int p0 = blockIdx.x * PB;

    {
        auto cp = [&](int dst, const float* src, int n) {
            for (int i = tid; i < n; i += NTHR) sm[dst + i] = src[i];
        };
        cp(S_FW1, fw1, 384);   cp(S_FB1, fb1, 128);
        cp(S_FW2, fw2, 16384); cp(S_FB2, fb2, 128);
        cp(S_FW3, fw3, 256);   cp(S_FB3, fb3, 2);
        cp(S_GW1, gw1, 256);   cp(S_GB1, gb1, 128);
        cp(S_GB2, gb2, 128);
        cp(S_GW3, gw3, 256);   cp(S_GB3, gb3, 2);
        cp(S_TS, ts, SEQ);
        for (int i = tid; i < 16384; i += NTHR)
            sm[S_GW2 + (i >> 7) * GWS + (i & 127)] = gw2[i];
    }
    if (tid < PB * 2) {
        float v = y0[p0 * 2 + tid];
        sm[S_YSH + tid] = v;
        out[(size_t)(p0 + (tid >> 1)) * (SEQ * 2) + (tid & 1)] = v;
    }
    __syncthreads();

    const int lane = tid & 31;
    const int warp = tid >> 5;
    // group A (warps 0-7): critical chain.  group B (warps 8-15): GEMM2.
    const int gt = tid & 255;
    const int pg = gt & 15;          // 16 path groups x 4 paths
    const int cg = gt >> 4;          // 16 col groups x 8 cols
    const int gw = warp & 7;         // warp within group

    for (int t = 0; t < NSTEP; ++t) {
        const float dt = sm[S_TS + t + 1] - sm[S_TS + t];
        const float sqdt = sqrtf(dt);

        // pass1 (all 512): H1 -> A, G1 -> B, dW prefetch
        if (tid < PB * 2)
            sm[S_DWV + tid] = dW[(size_t)t * (NPATHS * 2) + p0 * 2 + tid] * sqdt;
#pragma unroll
        for (int it = 0; it < 4; ++it) {
            int i4 = tid + it * NTHR;          // 2048 float4 tasks
            int j = i4 >> 4, pb = (i4 & 15) * 4;
            float4 y01 = *(const float4*)(sm + S_YSH + pb * 2);
            float4 y23 = *(const float4*)(sm + S_YSH + pb * 2 + 4);
            float fa = sm[S_FW1 + j], fb = sm[S_FW1 + 128 + j], fs = sm[S_FW1 + 256 + j];
            float fbb = sm[S_FB1 + j];
            float4 oF;
            oF.x = silu_(fbb + y01.x * fa + y01.y * fb + (y01.x - y01.y) * fs);
            oF.y = silu_(fbb + y01.z * fa + y01.w * fb + (y01.z - y01.w) * fs);
            oF.z = silu_(fbb + y23.x * fa + y23.y * fb + (y23.x - y23.y) * fs);
            oF.w = silu_(fbb + y23.z * fa + y23.w * fb + (y23.z - y23.w) * fs);
            *(float4*)(sm + S_A + j * PB + pb) = oF;
            float ga = sm[S_GW1 + j], gb = sm[S_GW1 + 128 + j], gbb = sm[S_GB1 + j];
            float4 oG;
            oG.x = silu_(gbb + y01.x * ga + y01.y * gb);
            oG.y = silu_(gbb + y01.z * ga + y01.w * gb);
            oG.z = silu_(gbb + y23.x * ga + y23.y * gb);
            oG.w = silu_(gbb + y23.z * ga + y23.w * gb);
            *(float4*)(sm + S_B + j * PB + pb) = oG;
        }
        __syncthreads();

        if (tid < 256) {
            // ===== group A: GEMM5 -> milstein -> pass8 -> GEMM9 =====
            float s2[16];   // dsilu(z2) kept in registers
            {
                unsigned long long acc[16] = {};
                gemm_fwd8(sm + S_B, sm + S_GW2, GWS, pg, cg, acc);
                float part[8] = {0, 0, 0, 0, 0, 0, 0, 0};
#pragma unroll
                for (int c = 0; c < 8; ++c) {
                    int j = cg * 8 + c;
                    float bb = sm[S_GB2 + j];
                    float w0 = sm[S_GW3 + j * 2], w1 = sm[S_GW3 + j * 2 + 1];
                    float2 a = upk(acc[2 * c]), b = upk(acc[2 * c + 1]);
                    float z0 = a.x + bb, z1 = a.y + bb, z2 = b.x + bb, z3 = b.y + bb;
                    float g0 = silu_(z0), g1 = silu_(z1), g2 = silu_(z2), g3 = silu_(z3);
                    part[0] += g0 * w0; part[1] += g0 * w1;
                    part[2] += g1 * w0; part[3] += g1 * w1;
                    part[4] += g2 * w0; part[5] += g2 * w1;
                    part[6] += g3 * w0; part[7] += g3 * w1;
                    s2[c * 2 + 0] = dsilu_t(z0); s2[c * 2 + 1] = dsilu_t(z1);
                    s2[16 / 2 + c] = 0.0f; // placeholder overwritten below (keeps layout simple)
                    s2[c * 2 + 0] = dsilu_t(z0);
                    s2[c * 2 + 1] = dsilu_t(z1);
                }
                // recompute layout cleanly: s2 indexed [c][q] as c*2 pairs is wrong for q=2,3;
                // redo with full 16-slot layout:
#pragma unroll
                for (int c = 0; c < 8; ++c) {
                    float bb = sm[S_GB2 + cg * 8 + c];
                    float2 a = upk(acc[2 * c]), b = upk(acc[2 * c + 1]);
                    s2[c * 2 + 0] = dsilu_t(a.x + bb);
                    s2[c * 2 + 1] = dsilu_t(a.y + bb);
                }
                // store the q=2,3 halves into B later via second pass using acc directly:
                // (handled in pass8 below with bhalf[])
                reduce16_store(part, sm + S_PR, lane, gw);
                // stash q=2,3 dsilu values in a second register array
                float s2b0, s2b1, s2b2, s2b3, s2b4, s2b5, s2b6, s2b7;
                {
                    float2 b0 = upk(acc[1]);  float bb0 = sm[S_GB2 + cg * 8 + 0];
                    s2b0 = dsilu_t(b0.x + bb0); s2b1 = dsilu_t(b0.y + bb0);
                }
                // NOTE: the above ad-hoc path is error-prone; use a uniform approach:
                // overwrite s2[] with all 16 values in [c][q] layout.
#pragma unroll
                for (int c = 0; c < 8; ++c) {
                    float bb = sm[S_GB2 + cg * 8 + c];
                    float2 a = upk(acc[2 * c]), b = upk(acc[2 * c + 1]);
                    s2[c * 2 + 0] = dsilu_t(a.x + bb);
                    s2[c * 2 + 1] = dsilu_t(a.y + bb);
                }
                (void)s2b0; (void)s2b1; (void)s2b2; (void)s2b3;
                (void)s2b4; (void)s2b5; (void)s2b6; (void)s2b7;
                // pass8 for q=2,3 needs dsilu(b.x+bb), dsilu(b.y+bb): recompute from acc
                // kept alive below via zacc[]
                float zacc[16];
#pragma unroll
                for (int c = 0; c < 8; ++c) {
                    float bb = sm[S_GB2 + cg * 8 + c];
                    float2 b = upk(acc[2 * c + 1]);
                    zacc[c * 2 + 0] = b.x + bb;
                    zacc[c * 2 + 1] = b.y + bb;
                }
                asm volatile("bar.sync 1, 256;" ::: "memory");

                // milstein per-path scalars (warps 0-3)
                if (tid < 128) {
                    float raw = sm[S_GB3 + (tid & 1)];
#pragma unroll
                    for (int g = 0; g < 8; ++g) raw += sm[S_PR + g * 128 + tid];
                    float dw = sm[S_DWV + tid];
                    float sp = fmaxf(raw, 0.0f) + log1pf(__expf(-fabsf(raw)));
                    float g = fminf(fmaxf(sp, MIN_VOL), MAX_VOL);
                    float mask = (sp > MIN_VOL && sp < MAX_VOL) ? 1.0f : 0.0f;
                    float v = 0.5f * (dw * dw - dt);
                    sm[S_DRW + tid] = v * g * sigm(raw) * mask;
                    sm[S_GV + tid] = g;
                }
                asm volatile("bar.sync 1, 256;" ::: "memory");

                // pass8: delta_z2 -> B (from registers)
                float4 dr01 = *(const float4*)(sm + S_DRW + pg * 8);
                float4 dr23 = *(const float4*)(sm + S_DRW + pg * 8 + 4);
#pragma unroll
                for (int c = 0; c < 8; ++c) {
                    int j = cg * 8 + c;
                    float g0 = sm[S_GW3 + j * 2], g1 = sm[S_GW3 + j * 2 + 1];
                    float4 o;
                    o.x = s2[c * 2 + 0] * (dr01.x * g0 + dr01.y * g1);
                    o.y = s2[c * 2 + 1] * (dr01.z * g0 + dr01.w * g1);
                    o.z = dsilu_t(zacc[c * 2 + 0]) * (dr23.x * g0 + dr23.y * g1);
                    o.w = dsilu_t(zacc[c * 2 + 1]) * (dr23.z * g0 + dr23.w * g1);
                    *(float4*)(sm + S_B + j * PB + pg * 4) = o;
                }
            }
            asm volatile("bar.sync 1, 256;" ::: "memory");

            // GEMM9: dz1 = (delta_z2 @ gw2^T) * dsilu(z1); corr-partials -> PC
            {
                unsigned long long acc[16] = {};
                gemm_bwd8(sm + S_B, sm + S_GW2, pg, cg, acc);
                float part[8] = {0, 0, 0, 0, 0, 0, 0, 0};
#pragma unroll
                for (int c = 0; c < 8; ++c) {
                    int i = cg * 8 + c;
                    float w0 = sm[S_GW1 + i], w1 = sm[S_GW1 + 128 + i], bb = sm[S_GB1 + i];
                    float2 a = upk(acc[2 * c]), b = upk(acc[2 * c + 1]);
                    float vv[4] = {a.x, a.y, b.x, b.y};
#pragma unroll
                    for (int q = 0; q < 4; ++q) {
                        int p = pg * 4 + q;
                        float z1 = sm[S_YSH + p * 2] * w0 + sm[S_YSH + p * 2 + 1] * w1 + bb;
                        float dz = vv[q] * dsilu_t(z1);
                        part[q * 2 + 0] += dz * w0;
                        part[q * 2 + 1] += dz * w1;
                    }
                }
                reduce16_store(part, sm + S_PC, lane, gw);
            }
        } else {
            // ===== group B: GEMM2 (drift), fully off the critical path =====
            unsigned long long acc[16] = {};
            gemm_fwd8(sm + S_A, sm + S_FW2, HID, pg, cg, acc);
            float part[8] = {0, 0, 0, 0, 0, 0, 0, 0};
#pragma unroll
            for (int c = 0; c < 8; ++c) {
                int j = cg * 8 + c;
                float bb = sm[S_FB2 + j];
                float w0 = sm[S_FW3 + j * 2], w1 = sm[S_FW3 + j * 2 + 1];
                float2 a = upk(acc[2 * c]), b = upk(acc[2 * c + 1]);
                float h0 = silu_(a.x + bb), h1 = silu_(a.y + bb);
                float h2 = silu_(b.x + bb), h3 = silu_(b.y + bb);
                part[0] += h0 * w0; part[1] += h0 * w1;
                part[2] += h1 * w0; part[3] += h1 * w1;
                part[4] += h2 * w0; part[5] += h2 * w1;
                part[6] += h3 * w0; part[7] += h3 * w1;
            }
            reduce16_store(part, sm + S_PF, lane, gw);
        }
        __syncthreads();

        // final (tid<128): y update + output
        if (tid < 128) {
            float fv = sm[S_FB3 + (tid & 1)], corr = 0.0f;
#pragma unroll
            for (int g = 0; g < 8; ++g) {
                fv += sm[S_PF + g * 128 + tid];
                corr += sm[S_PC + g * 128 + tid];
            }
            float y1 = sm[S_YSH + tid] + fv * dt
                     + sm[S_GV + tid] * sm[S_DWV + tid] + corr;
            sm[S_YSH + tid] = y1;
            out[(size_t)(p0 + (tid >> 1)) * (SEQ * 2) + (size_t)(t + 1) * 2 + (tid & 1)] = y1;
        }
        __syncthreads();
    }
}

extern "C" void kernel_launch(void* const* d_in, const int* in_sizes, int n_in,
                              void* d_out, int out_size) {
    (void)in_sizes; (void)n_in; (void)out_size;
    cudaFuncSetAttribute(sde_kernel, cudaFuncAttributeMaxDynamicSharedMemorySize, SMEM_BYTES);
    sde_kernel<<<NBLK, NTHR, SMEM_BYTES>>>(
        (const float*)d_in[0], (const float*)d_in[1], (const float*)d_in[2],
        (const float*)d_in[3], (const float*)d_in[4], (const float*)d_in[5],
        (const float*)d_in[6], (const float*)d_in[7], (const float*)d_in[8],
        (const float*)d_in[9], (const float*)d_in[10], (const float*)d_in[11],
        (const float*)d_in[12], (const float*)d_in[13], (const float*)d_in[14],
        (float*)d_out);
}

// round 14
// speedup vs baseline: 1.1845x; 1.0201x over previous
#include <cuda_runtime.h>
#include <math.h>

#define NPATHS 8192
#define SEQ    512
#define NSTEP  511
#define HID    128
#define PB     64
#define NTHR   512
#define NBLK   (NPATHS / PB)

#define MIN_VOL 1e-4f
#define MAX_VOL 5.0f

#define GWS 132   // padded row stride for gw2

// ---- shared memory layout (floats) ----
#define S_FW1 0
#define S_FB1 384
#define S_FW2 512
#define S_FB2 16896
#define S_FW3 17024
#define S_FB3 17280
#define S_GW1 17284
#define S_GB1 17540
#define S_GW2 17668          // 132*128 = 16896
#define S_GB2 34564
#define S_GW3 34692
#define S_GB3 34948
#define S_TS  34952
#define S_A   35464          // 8192: H1 (read-only during step)
#define S_B   43656          // 8192: G1 -> delta_z2
#define S_PF  51848          // 1024: f partials (8 warps x 128)
#define S_PRC 52872          // 2048: raw partials (8x128) then corr partials (16x128)
#define S_YSH 54920
#define S_GV  55048
#define S_DWV 55176
#define S_DRW 55304
#define S_TOT 55432
#define SMEM_BYTES (S_TOT * 4)

// ---- packed f32x2 helpers ----
__device__ __forceinline__ void ffma2(unsigned long long& d, unsigned long long a, unsigned long long b) {
    asm("fma.rn.f32x2 %0, %1, %2, %0;" : "+l"(d) : "l"(a), "l"(b));
}
__device__ __forceinline__ unsigned long long dup2(float w) {
    unsigned long long r;
    asm("mov.b64 %0, {%1, %1};" : "=l"(r) : "f"(w));
    return r;
}
__device__ __forceinline__ float2 upk(unsigned long long u) {
    float2 v;
    asm("mov.b64 {%0, %1}, %2;" : "=f"(v.x), "=f"(v.y) : "l"(u));
    return v;
}

// exp-based sigmoid (accurate; forward path)
__device__ __forceinline__ float sigm(float z) {
    return __fdividef(1.0f, 1.0f + __expf(-z));
}
__device__ __forceinline__ float silu_(float z) { return z * sigm(z); }

// tanh-based sigmoid (Milstein-correction dsilu factors only)
__device__ __forceinline__ float sigm_t(float z) {
    float th;
    asm("tanh.approx.f32 %0, %1;" : "=f"(th) : "f"(0.5f * z));
    return 0.5f * th + 0.5f;
}
__device__ __forceinline__ float dsilu_t(float z) {
    float s = sigm_t(z);
    return s * (1.0f + z * (1.0f - s));
}

// forward GEMM, thread tile 4 paths x 8 cols (256 threads cover 64x128)
__device__ __forceinline__ void gemm_fwd8(const float* __restrict__ sA,
                                          const float* __restrict__ sW, int ws,
                                          int pg, int cg, unsigned long long acc[16]) {
#pragma unroll 2
    for (int k4 = 0; k4 < HID; k4 += 4) {
        ulonglong2 h[4];
#pragma unroll
        for (int u = 0; u < 4; ++u)
            h[u] = *(const ulonglong2*)(sA + (k4 + u) * PB + pg * 4);
#pragma unroll
        for (int u = 0; u < 4; ++u) {
            float4 wa = *(const float4*)(sW + (k4 + u) * ws + cg * 8);
            float4 wb = *(const float4*)(sW + (k4 + u) * ws + cg * 8 + 4);
            unsigned long long d0 = dup2(wa.x), d1 = dup2(wa.y), d2 = dup2(wa.z), d3 = dup2(wa.w);
            unsigned long long d4 = dup2(wb.x), d5 = dup2(wb.y), d6 = dup2(wb.z), d7 = dup2(wb.w);
            ffma2(acc[0],  h[u].x, d0); ffma2(acc[1],  h[u].y, d0);
            ffma2(acc[2],  h[u].x, d1); ffma2(acc[3],  h[u].y, d1);
            ffma2(acc[4],  h[u].x, d2); ffma2(acc[5],  h[u].y, d2);
            ffma2(acc[6],  h[u].x, d3); ffma2(acc[7],  h[u].y, d3);
            ffma2(acc[8],  h[u].x, d4); ffma2(acc[9],  h[u].y, d4);
            ffma2(acc[10], h[u].x, d5); ffma2(acc[11], h[u].y, d5);
            ffma2(acc[12], h[u].x, d6); ffma2(acc[13], h[u].y, d6);
            ffma2(acc[14], h[u].x, d7); ffma2(acc[15], h[u].y, d7);
        }
    }
}

// backward GEMM over k range [k0, k0+64) (W transposed, rows stride GWS), tile 4x8
__device__ __forceinline__ void gemm_bwd8(const float* __restrict__ sB,
                                          const float* __restrict__ sW,
                                          int pg, int cg, int k0, unsigned long long acc[16]) {
#pragma unroll 2
    for (int kk = 0; kk < 64; kk += 4) {
        int k4 = k0 + kk;
        ulonglong2 h[4];
#pragma unroll
        for (int u = 0; u < 4; ++u)
            h[u] = *(const ulonglong2*)(sB + (k4 + u) * PB + pg * 4);
#pragma unroll
        for (int c = 0; c < 8; ++c) {
            float4 w = *(const float4*)(sW + (cg * 8 + c) * GWS + k4);
            unsigned long long wd;
            wd = dup2(w.x); ffma2(acc[2 * c], h[0].x, wd); ffma2(acc[2 * c + 1], h[0].y, wd);
            wd = dup2(w.y); ffma2(acc[2 * c], h[1].x, wd); ffma2(acc[2 * c + 1], h[1].y, wd);
            wd = dup2(w.z); ffma2(acc[2 * c], h[2].x, wd); ffma2(acc[2 * c + 1], h[2].y, wd);
            wd = dup2(w.w); ffma2(acc[2 * c], h[3].x, wd); ffma2(acc[2 * c + 1], h[3].y, wd);
        }
    }
}

// reduce partials over the 2 cg-subgroups of a warp (lane bit 4), store 8 floats/lane
__device__ __forceinline__ void reduce16_store(float part[8], float* __restrict__ dst,
                                               int lane, int w) {
#pragma unroll
    for (int v = 0; v < 8; ++v)
        part[v] += __shfl_xor_sync(0xffffffffu, part[v], 16);
    if (lane < 16) {
        float4 o0 = {part[0], part[1], part[2], part[3]};
        float4 o1 = {part[4], part[5], part[6], part[7]};
        *(float4*)(dst + w * 128 + lane * 8) = o0;
        *(float4*)(dst + w * 128 + lane * 8 + 4) = o1;
    }
}

__global__ void __launch_bounds__(NTHR, 1) sde_kernel(
    const float* __restrict__ y0, const float* __restrict__ ts, const float* __restrict__ dW,
    const float* __restrict__ fw1, const float* __restrict__ fb1,
    const float* __restrict__ fw2, const float* __restrict__ fb2,
    const float* __restrict__ fw3, const float* __restrict__ fb3,
    const float* __restrict__ gw1, const float* __restrict__ gb1,
    const float* __restrict__ gw2, const float* __restrict__ gb2,
    const float* __restrict__ gw3, const float* __restrict__ gb3,
    float* __restrict__ out) {
    extern __shared__ float sm[];
    const int tid = threadIdx.x;
    const int p0 = blockIdx.x * PB;

    {
        auto cp = [&](int dst, const float* src, int n) {
            for (int i = tid; i < n; i += NTHR) sm[dst + i] = src[i];
        };
        cp(S_FW1, fw1, 384);   cp(S_FB1, fb1, 128);
        cp(S_FW2, fw2, 16384); cp(S_FB2, fb2, 128);
        cp(S_FW3, fw3, 256);   cp(S_FB3, fb3, 2);
        cp(S_GW1, gw1, 256);   cp(S_GB1, gb1, 128);
        cp(S_GB2, gb2, 128);
        cp(S_GW3, gw3, 256);   cp(S_GB3, gb3, 2);
        cp(S_TS, ts, SEQ);
        for (int i = tid; i < 16384; i += NTHR)
            sm[S_GW2 + (i >> 7) * GWS + (i & 127)] = gw2[i];
    }
    if (tid < PB * 2) {
        float v = y0[p0 * 2 + tid];
        sm[S_YSH + tid] = v;
        out[(size_t)(p0 + (tid >> 1)) * (SEQ * 2) + (tid & 1)] = v;
    }
    __syncthreads();

    const int lane = tid & 31;
    const int warp = tid >> 5;
    const int gt = tid & 255;
    const int pg = gt & 15;          // 16 path groups x 4 paths
    const int cg = gt >> 4;          // 16 col groups x 8 cols
    const int gw = warp & 7;

    for (int t = 0; t < NSTEP; ++t) {
        const float dt = sm[S_TS + t + 1] - sm[S_TS + t];
        const float sqdt = sqrtf(dt);

        // pass1 (all 512): H1 -> A, G1 -> B, dW prefetch
        if (tid < PB * 2)
            sm[S_DWV + tid] = dW[(size_t)t * (NPATHS * 2) + p0 * 2 + tid] * sqdt;
#pragma unroll
        for (int it = 0; it < 4; ++it) {
            int i4 = tid + it * NTHR;          // 2048 float4 tasks
            int j = i4 >> 4, pb = (i4 & 15) * 4;
            float4 y01 = *(const float4*)(sm + S_YSH + pb * 2);
            float4 y23 = *(const float4*)(sm + S_YSH + pb * 2 + 4);
            float fa = sm[S_FW1 + j], fb = sm[S_FW1 + 128 + j], fs = sm[S_FW1 + 256 + j];
            float fbb = sm[S_FB1 + j];
            float4 oF;
            oF.x = silu_(fbb + y01.x * fa + y01.y * fb + (y01.x - y01.y) * fs);
            oF.y = silu_(fbb + y01.z * fa + y01.w * fb + (y01.z - y01.w) * fs);
            oF.z = silu_(fbb + y23.x * fa + y23.y * fb + (y23.x - y23.y) * fs);
            oF.w = silu_(fbb + y23.z * fa + y23.w * fb + (y23.z - y23.w) * fs);
            *(float4*)(sm + S_A + j * PB + pb) = oF;
            float ga = sm[S_GW1 + j], gb = sm[S_GW1 + 128 + j], gbb = sm[S_GB1 + j];
            float4 oG;
            oG.x = silu_(gbb + y01.x * ga + y01.y * gb);
            oG.y = silu_(gbb + y01.z * ga + y01.w * gb);
            oG.z = silu_(gbb + y23.x * ga + y23.y * gb);
            oG.w = silu_(gbb + y23.z * ga + y23.w * gb);
            *(float4*)(sm + S_B + j * PB + pb) = oG;
        }
        __syncthreads();

        if (tid < 256) {
            // ===== group A: GEMM5 -> milstein -> pass8 =====
            float z2v[32];   // full pre-activations of layer-2 diffusion, in registers
            {
                unsigned long long acc[16] = {};
                gemm_fwd8(sm + S_B, sm + S_GW2, GWS, pg, cg, acc);
                float part[8] = {0, 0, 0, 0, 0, 0, 0, 0};
#pragma unroll
                for (int c = 0; c < 8; ++c) {
                    int j = cg * 8 + c;
                    float bb = sm[S_GB2 + j];
                    float w0 = sm[S_GW3 + j * 2], w1 = sm[S_GW3 + j * 2 + 1];
                    float2 a = upk(acc[2 * c]), b = upk(acc[2 * c + 1]);
                    float z0 = a.x + bb, z1 = a.y + bb, z2 = b.x + bb, z3 = b.y + bb;
                    z2v[c * 4 + 0] = z0; z2v[c * 4 + 1] = z1;
                    z2v[c * 4 + 2] = z2; z2v[c * 4 + 3] = z3;
                    float g0 = silu_(z0), g1 = silu_(z1), g2 = silu_(z2), g3 = silu_(z3);
                    part[0] += g0 * w0; part[1] += g0 * w1;
                    part[2] += g1 * w0; part[3] += g1 * w1;
                    part[4] += g2 * w0; part[5] += g2 * w1;
                    part[6] += g3 * w0; part[7] += g3 * w1;
                }
                reduce16_store(part, sm + S_PRC, lane, gw);
            }
            asm volatile("bar.sync 1, 256;" ::: "memory");

            // milstein per-path scalars (warps 0-3)
            if (tid < 128) {
                float raw = sm[S_GB3 + (tid & 1)];
#pragma unroll
                for (int g = 0; g < 8; ++g) raw += sm[S_PRC + g * 128 + tid];
                float dw = sm[S_DWV + tid];
                float sp = fmaxf(raw, 0.0f) + log1pf(__expf(-fabsf(raw)));
                float g = fminf(fmaxf(sp, MIN_VOL), MAX_VOL);
                float mask = (sp > MIN_VOL && sp < MAX_VOL) ? 1.0f : 0.0f;
                float v = 0.5f * (dw * dw - dt);
                sm[S_DRW + tid] = v * g * sigm(raw) * mask;
                sm[S_GV + tid] = g;
            }
            asm volatile("bar.sync 1, 256;" ::: "memory");

            // pass8: delta_z2 = dsilu(z2) * (delta_raw @ gw3^T) -> B
            {
                float4 dr01 = *(const float4*)(sm + S_DRW + pg * 8);
                float4 dr23 = *(const float4*)(sm + S_DRW + pg * 8 + 4);
#pragma unroll
                for (int c = 0; c < 8; ++c) {
                    int j = cg * 8 + c;
                    float g0 = sm[S_GW3 + j * 2], g1 = sm[S_GW3 + j * 2 + 1];
                    float4 o;
                    o.x = dsilu_t(z2v[c * 4 + 0]) * (dr01.x * g0 + dr01.y * g1);
                    o.y = dsilu_t(z2v[c * 4 + 1]) * (dr01.z * g0 + dr01.w * g1);
                    o.z = dsilu_t(z2v[c * 4 + 2]) * (dr23.x * g0 + dr23.y * g1);
                    o.w = dsilu_t(z2v[c * 4 + 3]) * (dr23.z * g0 + dr23.w * g1);
                    *(float4*)(sm + S_B + j * PB + pg * 4) = o;
                }
            }
        } else {
            // ===== group B: GEMM2 (drift), off the critical path =====
            unsigned long long acc[16] = {};
            gemm_fwd8(sm + S_A, sm + S_FW2, HID, pg, cg, acc);
            float part[8] = {0, 0, 0, 0, 0, 0, 0, 0};
#pragma unroll
            for (int c = 0; c < 8; ++c) {
                int j = cg * 8 + c;
                float bb = sm[S_FB2 + j];
                float w0 = sm[S_FW3 + j * 2], w1 = sm[S_FW3 + j * 2 + 1];
                float2 a = upk(acc[2 * c]), b = upk(acc[2 * c + 1]);
                float h0 = silu_(a.x + bb), h1 = silu_(a.y + bb);
                float h2 = silu_(b.x + bb), h3 = silu_(b.y + bb);
                part[0] += h0 * w0; part[1] += h0 * w1;
                part[2] += h1 * w0; part[3] += h1 * w1;
                part[4] += h2 * w0; part[5] += h2 * w1;
                part[6] += h3 * w0; part[7] += h3 * w1;
            }
            reduce16_store(part, sm + S_PF, lane, gw);
        }
        __syncthreads();

        // GEMM9 on ALL 16 warps, k-split (epilogue is linear in acc):
        // dz1 = (delta_z2 @ gw2^T)|k-half * dsilu(z1); corr-partials -> PRC[warp]
        {
            int k0 = (warp >> 3) << 6;       // 0 for warps 0-7, 64 for warps 8-15
            unsigned long long acc[16] = {};
            gemm_bwd8(sm + S_B, sm + S_GW2, pg, cg, k0, acc);
            float part[8] = {0, 0, 0, 0, 0, 0, 0, 0};
#pragma unroll
            for (int c = 0; c < 8; ++c) {
                int i = cg * 8 + c;
                float w0 = sm[S_GW1 + i], w1 = sm[S_GW1 + 128 + i], bb = sm[S_GB1 + i];
                float2 a = upk(acc[2 * c]), b = upk(acc[2 * c + 1]);
                float vv[4] = {a.x, a.y, b.x, b.y};
#pragma unroll
                for (int q = 0; q < 4; ++q) {
                    int p = pg * 4 + q;
                    float z1 = sm[S_YSH + p * 2] * w0 + sm[S_YSH + p * 2 + 1] * w1 + bb;
                    float dz = vv[q] * dsilu_t(z1);
                    part[q * 2 + 0] += dz * w0;
                    part[q * 2 + 1] += dz * w1;
                }
            }
            reduce16_store(part, sm + S_PRC, lane, warp);
        }
        __syncthreads();

        // final (tid<128): y update + output
        if (tid < 128) {
            float fv = sm[S_FB3 + (tid & 1)], corr = 0.0f;
#pragma unroll
            for (int g = 0; g < 8; ++g) fv += sm[S_PF + g * 128 + tid];
#pragma unroll
            for (int g = 0; g < 16; ++g) corr += sm[S_PRC + g * 128 + tid];
            float y1 = sm[S_YSH + tid] + fv * dt
                     + sm[S_GV + tid] * sm[S_DWV + tid] + corr;
            sm[S_YSH + tid] = y1;
            out[(size_t)(p0 + (tid >> 1)) * (SEQ * 2) + (size_t)(t + 1) * 2 + (tid & 1)] = y1;
        }
        __syncthreads();
    }
}

extern "C" void kernel_launch(void* const* d_in, const int* in_sizes, int n_in,
                              void* d_out, int out_size) {
    (void)in_sizes; (void)n_in; (void)out_size;
    cudaFuncSetAttribute(sde_kernel, cudaFuncAttributeMaxDynamicSharedMemorySize, SMEM_BYTES);
    sde_kernel<<<NBLK, NTHR, SMEM_BYTES>>>(
        (const float*)d_in[0], (const float*)d_in[1], (const float*)d_in[2],
        (const float*)d_in[3], (const float*)d_in[4], (const float*)d_in[5],
        (const float*)d_in[6], (const float*)d_in[7], (const float*)d_in[8],
        (const float*)d_in[9], (const float*)d_in[10], (const float*)d_in[11],
        (const float*)d_in[12], (const float*)d_in[13], (const float*)d_in[14],
        (float*)d_out);
}

// round 17
// speedup vs baseline: 1.2193x; 1.0294x over previous
#include <cuda_runtime.h>
#include <math.h>

#define NPATHS 8192
#define SEQ    512
#define NSTEP  511
#define HID    128
#define PB     64
#define NTHR   512
#define NBLK   (NPATHS / PB)

#define MIN_VOL 1e-4f
#define MAX_VOL 5.0f

#define GWS 132   // padded row stride for gw2

// ---- shared memory layout (floats) ----
#define S_FW1 0
#define S_FB1 384
#define S_FW2 512
#define S_FB2 16896
#define S_FW3 17024
#define S_FB3 17280
#define S_GW1 17284
#define S_GB1 17540
#define S_GW2 17668          // 132*128 = 16896
#define S_GB2 34564
#define S_GW3 34692
#define S_GB3 34948
#define S_TS  34952
#define S_A   35464          // 8192: H1 (read-only during step)
#define S_B   43656          // 8192: G1 -> delta_z2
#define S_PF  51848          // 1024: f partials (8 warps x 128)
#define S_PRC 52872          // 2048: raw partials (8x128) then corr partials (16x128)
#define S_YSH 54920
#define S_GV  55048
#define S_DWV 55176
#define S_DRW 55304
#define S_TOT 55432
#define SMEM_BYTES (S_TOT * 4)

// ---- packed f32x2 helpers ----
__device__ __forceinline__ void ffma2(unsigned long long& d, unsigned long long a, unsigned long long b) {
    asm("fma.rn.f32x2 %0, %1, %2, %0;" : "+l"(d) : "l"(a), "l"(b));
}
__device__ __forceinline__ unsigned long long dup2(float w) {
    unsigned long long r;
    asm("mov.b64 %0, {%1, %1};" : "=l"(r) : "f"(w));
    return r;
}
__device__ __forceinline__ float2 upk(unsigned long long u) {
    float2 v;
    asm("mov.b64 {%0, %1}, %2;" : "=f"(v.x), "=f"(v.y) : "l"(u));
    return v;
}

// exp-based sigmoid (accurate; forward path)
__device__ __forceinline__ float sigm(float z) {
    return __fdividef(1.0f, 1.0f + __expf(-z));
}
__device__ __forceinline__ float silu_(float z) { return z * sigm(z); }

// tanh-based sigmoid (Milstein-correction dsilu factors only)
__device__ __forceinline__ float sigm_t(float z) {
    float th;
    asm("tanh.approx.f32 %0, %1;" : "=f"(th) : "f"(0.5f * z));
    return 0.5f * th + 0.5f;
}
__device__ __forceinline__ float dsilu_t(float z) {
    float s = sigm_t(z);
    return s * (1.0f + z * (1.0f - s));
}

// forward GEMM, h-dup / column-pair layout.
// acc[p*4+cc] = f32x2 over cols (cg*8+2cc, cg*8+2cc+1) for path pg*4+p.
// Per k: 1 float4 LDS (4 paths) + 2 LDS.128 (8 cols as 4 natural u64 pairs)
//        + 4 dup2 + 16 FFMA2.
__device__ __forceinline__ void gemm_fwd_hd(const float* __restrict__ sA,
                                            const float* __restrict__ sW, int ws,
                                            int pg, int cg, unsigned long long acc[16]) {
#pragma unroll 2
    for (int k4 = 0; k4 < HID; k4 += 4) {
#pragma unroll
        for (int u = 0; u < 4; ++u) {
            int k = k4 + u;
            float4 hv = *(const float4*)(sA + k * PB + pg * 4);
            ulonglong2 wA = *(const ulonglong2*)(sW + k * ws + cg * 8);
            ulonglong2 wB = *(const ulonglong2*)(sW + k * ws + cg * 8 + 4);
            unsigned long long h0 = dup2(hv.x), h1 = dup2(hv.y), h2 = dup2(hv.z), h3 = dup2(hv.w);
            ffma2(acc[0],  h0, wA.x); ffma2(acc[1],  h0, wA.y);
            ffma2(acc[2],  h0, wB.x); ffma2(acc[3],  h0, wB.y);
            ffma2(acc[4],  h1, wA.x); ffma2(acc[5],  h1, wA.y);
            ffma2(acc[6],  h1, wB.x); ffma2(acc[7],  h1, wB.y);
            ffma2(acc[8],  h2, wA.x); ffma2(acc[9],  h2, wA.y);
            ffma2(acc[10], h2, wB.x); ffma2(acc[11], h2, wB.y);
            ffma2(acc[12], h3, wA.x); ffma2(acc[13], h3, wA.y);
            ffma2(acc[14], h3, wB.x); ffma2(acc[15], h3, wB.y);
        }
    }
}

// backward GEMM over k range [k0, k0+64) (W transposed, rows stride GWS), tile 4x8,
// path-pair layout (acc[2c], acc[2c+1] = paths (0,1),(2,3) for col cg*8+c)
__device__ __forceinline__ void gemm_bwd8(const float* __restrict__ sB,
                                          const float* __restrict__ sW,
                                          int pg, int cg, int k0, unsigned long long acc[16]) {
#pragma unroll 2
    for (int kk = 0; kk < 64; kk += 4) {
        int k4 = k0 + kk;
        ulonglong2 h[4];
#pragma unroll
        for (int u = 0; u < 4; ++u)
            h[u] = *(const ulonglong2*)(sB + (k4 + u) * PB + pg * 4);
#pragma unroll
        for (int c = 0; c < 8; ++c) {
            float4 w = *(const float4*)(sW + (cg * 8 + c) * GWS + k4);
            unsigned long long wd;
            wd = dup2(w.x); ffma2(acc[2 * c], h[0].x, wd); ffma2(acc[2 * c + 1], h[0].y, wd);
            wd = dup2(w.y); ffma2(acc[2 * c], h[1].x, wd); ffma2(acc[2 * c + 1], h[1].y, wd);
            wd = dup2(w.z); ffma2(acc[2 * c], h[2].x, wd); ffma2(acc[2 * c + 1], h[2].y, wd);
            wd = dup2(w.w); ffma2(acc[2 * c], h[3].x, wd); ffma2(acc[2 * c + 1], h[3].y, wd);
        }
    }
}

// reduce partials over the 2 cg-subgroups of a warp (lane bit 4), store 8 floats/lane
__device__ __forceinline__ void reduce16_store(float part[8], float* __restrict__ dst,
                                               int lane, int w) {
#pragma unroll
    for (int v = 0; v < 8; ++v)
        part[v] += __shfl_xor_sync(0xffffffffu, part[v], 16);
    if (lane < 16) {
        float4 o0 = {part[0], part[1], part[2], part[3]};
        float4 o1 = {part[4], part[5], part[6], part[7]};
        *(float4*)(dst + w * 128 + lane * 8) = o0;
        *(float4*)(dst + w * 128 + lane * 8 + 4) = o1;
    }
}

__global__ void __launch_bounds__(NTHR, 1) sde_kernel(
    const float* __restrict__ y0, const float* __restrict__ ts, const float* __restrict__ dW,
    const float* __restrict__ fw1, const float* __restrict__ fb1,
    const float* __restrict__ fw2, const float* __restrict__ fb2,
    const float* __restrict__ fw3, const float* __restrict__ fb3,
    const float* __restrict__ gw1, const float* __restrict__ gb1,
    const float* __restrict__ gw2, const float* __restrict__ gb2,
    const float* __restrict__ gw3, const float* __restrict__ gb3,
    float* __restrict__ out) {
    extern __shared__ float sm[];
    const int tid = threadIdx.x;
    const int p0 = blockIdx.x * PB;

    {
        auto cp = [&](int dst, const float* src, int n) {
            for (int i = tid; i < n; i += NTHR) sm[dst + i] = src[i];
        };
        cp(S_FW1, fw1, 384);   cp(S_FB1, fb1, 128);
        cp(S_FW2, fw2, 16384); cp(S_FB2, fb2, 128);
        cp(S_FW3, fw3, 256);   cp(S_FB3, fb3, 2);
        cp(S_GW1, gw1, 256);   cp(S_GB1, gb1, 128);
        cp(S_GB2, gb2, 128);
        cp(S_GW3, gw3, 256);   cp(S_GB3, gb3, 2);
        cp(S_TS, ts, SEQ);
        for (int i = tid; i < 16384; i += NTHR)
            sm[S_GW2 + (i >> 7) * GWS + (i & 127)] = gw2[i];
    }
    if (tid < PB * 2) {
        float v = y0[p0 * 2 + tid];
        sm[S_YSH + tid] = v;
        out[(size_t)(p0 + (tid >> 1)) * (SEQ * 2) + (tid & 1)] = v;
    }
    __syncthreads();

    const int lane = tid & 31;
    const int warp = tid >> 5;
    const int gt = tid & 255;
    const int pg = gt & 15;          // 16 path groups x 4 paths
    const int cg = gt >> 4;          // 16 col groups x 8 cols
    const int gw = warp & 7;

    for (int t = 0; t < NSTEP; ++t) {
        const float dt = sm[S_TS + t + 1] - sm[S_TS + t];
        const float sqdt = sqrtf(dt);

        // pass1 (all 512): H1 -> A, G1 -> B, dW prefetch
        if (tid < PB * 2)
            sm[S_DWV + tid] = dW[(size_t)t * (NPATHS * 2) + p0 * 2 + tid] * sqdt;
#pragma unroll
        for (int it = 0; it < 4; ++it) {
            int i4 = tid + it * NTHR;          // 2048 float4 tasks
            int j = i4 >> 4, pb = (i4 & 15) * 4;
            float4 y01 = *(const float4*)(sm + S_YSH + pb * 2);
            float4 y23 = *(const float4*)(sm + S_YSH + pb * 2 + 4);
            float fa = sm[S_FW1 + j], fb = sm[S_FW1 + 128 + j], fs = sm[S_FW1 + 256 + j];
            float fbb = sm[S_FB1 + j];
            float4 oF;
            oF.x = silu_(fbb + y01.x * fa + y01.y * fb + (y01.x - y01.y) * fs);
            oF.y = silu_(fbb + y01.z * fa + y01.w * fb + (y01.z - y01.w) * fs);
            oF.z = silu_(fbb + y23.x * fa + y23.y * fb + (y23.x - y23.y) * fs);
            oF.w = silu_(fbb + y23.z * fa + y23.w * fb + (y23.z - y23.w) * fs);
            *(float4*)(sm + S_A + j * PB + pb) = oF;
            float ga = sm[S_GW1 + j], gb = sm[S_GW1 + 128 + j], gbb = sm[S_GB1 + j];
            float4 oG;
            oG.x = silu_(gbb + y01.x * ga + y01.y * gb);
            oG.y = silu_(gbb + y01.z * ga + y01.w * gb);
            oG.z = silu_(gbb + y23.x * ga + y23.y * gb);
            oG.w = silu_(gbb + y23.z * ga + y23.w * gb);
            *(float4*)(sm + S_B + j * PB + pb) = oG;
        }
        __syncthreads();

        if (tid < 256) {
            // ===== group A: GEMM5 -> milstein -> pass8 =====
            float z2v[32];   // z2 pre-activations, layout [c][p] (c = 0..7, p = 0..3)
            {
                unsigned long long acc[16] = {};
                gemm_fwd_hd(sm + S_B, sm + S_GW2, GWS, pg, cg, acc);
                float part[8] = {0, 0, 0, 0, 0, 0, 0, 0};
#pragma unroll
                for (int p = 0; p < 4; ++p) {
#pragma unroll
                    for (int cc = 0; cc < 4; ++cc) {
                        int j0 = cg * 8 + cc * 2, j1 = j0 + 1;
                        float2 z = upk(acc[p * 4 + cc]);
                        float z0 = z.x + sm[S_GB2 + j0], z1 = z.y + sm[S_GB2 + j1];
                        z2v[(cc * 2) * 4 + p] = z0;
                        z2v[(cc * 2 + 1) * 4 + p] = z1;
                        float g0 = silu_(z0), g1 = silu_(z1);
                        part[p * 2 + 0] += g0 * sm[S_GW3 + j0 * 2] + g1 * sm[S_GW3 + j1 * 2];
                        part[p * 2 + 1] += g0 * sm[S_GW3 + j0 * 2 + 1] + g1 * sm[S_GW3 + j1 * 2 + 1];
                    }
                }
                reduce16_store(part, sm + S_PRC, lane, gw);
            }
            asm volatile("bar.sync 1, 256;" ::: "memory");

            // milstein per-path scalars (warps 0-3)
            if (tid < 128) {
                float raw = sm[S_GB3 + (tid & 1)];
#pragma unroll
                for (int g = 0; g < 8; ++g) raw += sm[S_PRC + g * 128 + tid];
                float dw = sm[S_DWV + tid];
                float sp = fmaxf(raw, 0.0f) + __logf(1.0f + __expf(-fabsf(raw)));
                float g = fminf(fmaxf(sp, MIN_VOL), MAX_VOL);
                float mask = (sp > MIN_VOL && sp < MAX_VOL) ? 1.0f : 0.0f;
                float v = 0.5f * (dw * dw - dt);
                sm[S_DRW + tid] = v * g * sigm(raw) * mask;
                sm[S_GV + tid] = g;
            }
            asm volatile("bar.sync 1, 256;" ::: "memory");

            // pass8: delta_z2 = dsilu(z2) * (delta_raw @ gw3^T) -> B
            {
                float4 dr01 = *(const float4*)(sm + S_DRW + pg * 8);
                float4 dr23 = *(const float4*)(sm + S_DRW + pg * 8 + 4);
#pragma unroll
                for (int c = 0; c < 8; ++c) {
                    int j = cg * 8 + c;
                    float g0 = sm[S_GW3 + j * 2], g1 = sm[S_GW3 + j * 2 + 1];
                    float4 o;
                    o.x = dsilu_t(z2v[c * 4 + 0]) * (dr01.x * g0 + dr01.y * g1);
                    o.y = dsilu_t(z2v[c * 4 + 1]) * (dr01.z * g0 + dr01.w * g1);
                    o.z = dsilu_t(z2v[c * 4 + 2]) * (dr23.x * g0 + dr23.y * g1);
                    o.w = dsilu_t(z2v[c * 4 + 3]) * (dr23.z * g0 + dr23.w * g1);
                    *(float4*)(sm + S_B + j * PB + pg * 4) = o;
                }
            }
        } else {
            // ===== group B: GEMM2 (drift), off the critical path =====
            unsigned long long acc[16] = {};
            gemm_fwd_hd(sm + S_A, sm + S_FW2, HID, pg, cg, acc);
            float part[8] = {0, 0, 0, 0, 0, 0, 0, 0};
#pragma unroll
            for (int p = 0; p < 4; ++p) {
#pragma unroll
                for (int cc = 0; cc < 4; ++cc) {
                    int j0 = cg * 8 + cc * 2, j1 = j0 + 1;
                    float2 z = upk(acc[p * 4 + cc]);
                    float h0 = silu_(z.x + sm[S_FB2 + j0]);
                    float h1 = silu_(z.y + sm[S_FB2 + j1]);
                    part[p * 2 + 0] += h0 * sm[S_FW3 + j0 * 2] + h1 * sm[S_FW3 + j1 * 2];
                    part[p * 2 + 1] += h0 * sm[S_FW3 + j0 * 2 + 1] + h1 * sm[S_FW3 + j1 * 2 + 1];
                }
            }
            reduce16_store(part, sm + S_PF, lane, gw);
        }
        __syncthreads();

        // GEMM9 on ALL 16 warps, k-split (epilogue is linear in acc):
        // dz1 = (delta_z2 @ gw2^T)|k-half * dsilu(z1); corr-partials -> PRC[warp]
        {
            int k0 = (warp >> 3) << 6;       // 0 for warps 0-7, 64 for warps 8-15
            unsigned long long acc[16] = {};
            gemm_bwd8(sm + S_B, sm + S_GW2, pg, cg, k0, acc);
            float part[8] = {0, 0, 0, 0, 0, 0, 0, 0};
#pragma unroll
            for (int c = 0; c < 8; ++c) {
                int i = cg * 8 + c;
                float w0 = sm[S_GW1 + i], w1 = sm[S_GW1 + 128 + i], bb = sm[S_GB1 + i];
                float2 a = upk(acc[2 * c]), b = upk(acc[2 * c + 1]);
                float vv[4] = {a.x, a.y, b.x, b.y};
#pragma unroll
                for (int q = 0; q < 4; ++q) {
                    int p = pg * 4 + q;
                    float z1 = sm[S_YSH + p * 2] * w0 + sm[S_YSH + p * 2 + 1] * w1 + bb;
                    float dz = vv[q] * dsilu_t(z1);
                    part[q * 2 + 0] += dz * w0;
                    part[q * 2 + 1] += dz * w1;
                }
            }
            reduce16_store(part, sm + S_PRC, lane, warp);
        }
        __syncthreads();

        // final (tid<128): y update + output
        if (tid < 128) {
            float fv = sm[S_FB3 + (tid & 1)], corr = 0.0f;
#pragma unroll
            for (int g = 0; g < 8; ++g) fv += sm[S_PF + g * 128 + tid];
#pragma unroll
            for (int g = 0; g < 16; ++g) corr += sm[S_PRC + g * 128 + tid];
            float y1 = sm[S_YSH + tid] + fv * dt
                     + sm[S_GV + tid] * sm[S_DWV + tid] + corr;
            sm[S_YSH + tid] = y1;
            out[(size_t)(p0 + (tid >> 1)) * (SEQ * 2) + (size_t)(t + 1) * 2 + (tid & 1)] = y1;
        }
        __syncthreads();
    }
}

extern "C" void kernel_launch(void* const* d_in, const int* in_sizes, int n_in,
                              void* d_out, int out_size) {
    (void)in_sizes; (void)n_in; (void)out_size;
    cudaFuncSetAttribute(sde_kernel, cudaFuncAttributeMaxDynamicSharedMemorySize, SMEM_BYTES);
    sde_kernel<<<NBLK, NTHR, SMEM_BYTES>>>(
        (const float*)d_in[0], (const float*)d_in[1], (const float*)d_in[2],
        (const float*)d_in[3], (const float*)d_in[4], (const float*)d_in[5],
        (const float*)d_in[6], (const float*)d_in[7], (const float*)d_in[8],
        (const float*)d_in[9], (const float*)d_in[10], (const float*)d_in[11],
        (const float*)d_in[12], (const float*)d_in[13], (const float*)d_in[14],
        (float*)d_out);
}